// round 10
// baseline (speedup 1.0000x reference)
#include <cuda_runtime.h>
#include <cuda_bf16.h>
#include <cstdint>

// TopKRoute: y = x.reshape(64, 786432) @ W^T + b ; scatter top-k ; softmax(64)
// Round 10: warp-specialized split-bf16 HMMA GEMM, TILE_K=128 (512B bursts
// per row-stream, half the concurrent streams), 1 CTA/SM x 512 threads,
// 3-stage 64KB ring (192KB smem).

#define K_TOTAL     786432
#define NBLK        148
#define TILE_K      128
#define TILES_TOTAL (K_TOTAL / TILE_K)        // 6144
#define BASE_T      (TILES_TOTAL / NBLK)      // 41
#define EXTRA_T     (TILES_TOTAL % NBLK)      // 76

#define NSTAGE 3
#define BUF_BYTES 65536
// regions within one 64KB stage buffer (each sub-tile: 64 rows x 128B):
#define XH0 0
#define XL0 16384
#define WH0 32768
#define WL0 49152
// sub-tile k=64..127 lives at +8192 within each region

#define BAR_FULL  1
#define BAR_EMPTY 4
#define BAR_CONS  7

__device__ float g_partials[NBLK * 64 * 64];   // 2.4 MB
__device__ float g_s1[32 * 64 * 64];           // stage-1 reduced partials

// ---------------- helpers ----------------

__device__ __forceinline__ uint32_t smem_u32(const void* p) {
    return (uint32_t)__cvta_generic_to_shared(p);
}

__device__ __forceinline__ void bar_sync(int id, int cnt) {
    asm volatile("bar.sync %0, %1;" :: "r"(id), "r"(cnt) : "memory");
}
__device__ __forceinline__ void bar_arrive(int id, int cnt) {
    asm volatile("bar.arrive %0, %1;" :: "r"(id), "r"(cnt) : "memory");
}

__device__ __forceinline__ void ldsm4(uint32_t* r, uint32_t addr) {
    asm volatile("ldmatrix.sync.aligned.m8n8.x4.shared.b16 {%0,%1,%2,%3}, [%4];"
                 : "=r"(r[0]), "=r"(r[1]), "=r"(r[2]), "=r"(r[3]) : "r"(addr));
}

__device__ __forceinline__ void mma16816(float* c, const uint32_t* a,
                                         uint32_t b0, uint32_t b1) {
    asm volatile(
        "mma.sync.aligned.m16n8k16.row.col.f32.bf16.bf16.f32 "
        "{%0,%1,%2,%3}, {%4,%5,%6,%7}, {%8,%9}, {%0,%1,%2,%3};"
        : "+f"(c[0]), "+f"(c[1]), "+f"(c[2]), "+f"(c[3])
        : "r"(a[0]), "r"(a[1]), "r"(a[2]), "r"(a[3]), "r"(b0), "r"(b1));
}

__device__ __forceinline__ void split4(float4 v, uint2& hi, uint2& lo) {
    __nv_bfloat162 h0 = __float22bfloat162_rn(make_float2(v.x, v.y));
    __nv_bfloat162 h1 = __float22bfloat162_rn(make_float2(v.z, v.w));
    float2 f0 = __bfloat1622float2(h0);
    float2 f1 = __bfloat1622float2(h1);
    __nv_bfloat162 l0 = __float22bfloat162_rn(make_float2(v.x - f0.x, v.y - f0.y));
    __nv_bfloat162 l1 = __float22bfloat162_rn(make_float2(v.z - f1.x, v.w - f1.y));
    hi.x = *(uint32_t*)&h0;  hi.y = *(uint32_t*)&h1;
    lo.x = *(uint32_t*)&l0;  lo.y = *(uint32_t*)&l1;
}

__device__ __forceinline__ uint32_t sw128(uint32_t off) {
    return off ^ ((off >> 3) & 0x70);
}

// ---------------- GEMM kernel ----------------

extern __shared__ char dsmem[];

__global__ __launch_bounds__(512, 1) void gemm_ws_kernel(
    const float* __restrict__ x, const float* __restrict__ W) {
    const int tid  = threadIdx.x;
    const int wid  = tid >> 5;
    const int lane = tid & 31;
    const int bid  = blockIdx.x;

    const int t0  = BASE_T * bid + (bid < EXTRA_T ? bid : EXTRA_T);
    const int cnt = BASE_T + (bid < EXTRA_T ? 1 : 0);
    const long kbase = (long)t0 * TILE_K;

    if (wid < 8) {
        // ============ PRODUCER: 256 threads ============
        // q = tid&31 covers one full 512B row-chunk (32 float4) across a warp;
        // rb = tid>>5 (0..7); rows rb + 8i, i in 0..7.
        const int q    = tid & 31;
        const int rb   = tid >> 5;
        const int ksub = q >> 4;           // 0: k 0-63, 1: k 64-127
        const int qq   = q & 15;
        const float* xp = x + (long)rb * K_TOTAL + kbase + q * 4;
        const float* wp = W + (long)rb * K_TOTAL + kbase + q * 4;
        const long rstep = 8L * K_TOTAL;

        const uint32_t sub = (uint32_t)(ksub * 8192);
        uint32_t soff[8];
#pragma unroll
        for (int i = 0; i < 8; ++i)
            soff[i] = sub + sw128((uint32_t)((rb + 8 * i) * 128 + qq * 8));

        int b = 0;
        for (int t = 0; t < cnt; ++t) {
            if (t >= NSTAGE) bar_sync(BAR_EMPTY + b, 512);
            char* buf = dsmem + b * BUF_BYTES;
            const long koff = (long)t * TILE_K;

            float4 vx[8], vw[8];
#pragma unroll
            for (int i = 0; i < 8; ++i)
                vx[i] = *(const float4*)(xp + i * rstep + koff);
#pragma unroll
            for (int i = 0; i < 8; ++i)
                vw[i] = *(const float4*)(wp + i * rstep + koff);

#pragma unroll
            for (int i = 0; i < 8; ++i) {
                uint2 hi, lo;
                split4(vx[i], hi, lo);
                *(uint2*)(buf + XH0 + soff[i]) = hi;
                *(uint2*)(buf + XL0 + soff[i]) = lo;
            }
#pragma unroll
            for (int i = 0; i < 8; ++i) {
                uint2 hi, lo;
                split4(vw[i], hi, lo);
                *(uint2*)(buf + WH0 + soff[i]) = hi;
                *(uint2*)(buf + WL0 + soff[i]) = lo;
            }

            bar_arrive(BAR_FULL + b, 512);
            b = (b + 1 == NSTAGE) ? 0 : b + 1;
        }
    } else {
        // ============ CONSUMER: 8 warps = 2x2 spatial x 2 k-split ============
        const int cwid = wid - 8;
        const int wk = cwid >> 2;          // k-subtile 0 or 1
        const int wr = (cwid >> 1) & 1;
        const int wc = cwid & 1;
        const int r0 = wr * 32;
        const int c0 = wc * 32;

        const uint32_t s0 = smem_u32(dsmem);
        const int arow0 = r0 + (lane & 15);
        const int bcol0 = c0 + (lane & 15);
        const uint32_t axm   = (uint32_t)((arow0 & 7) * 16);
        const uint32_t bxm   = (uint32_t)((bcol0 & 7) * 16);
        const uint32_t khalf = (uint32_t)((lane >> 4) * 16);
        const uint32_t sub   = (uint32_t)(wk * 8192);

        const uint32_t aoff0 = (uint32_t)(arow0 * 128) + sub;
        const uint32_t aoff1 = (uint32_t)((arow0 + 16) * 128) + sub;
        const uint32_t boff0 = (uint32_t)(bcol0 * 128) + sub;
        const uint32_t boff1 = (uint32_t)((bcol0 + 16) * 128) + sub;

        float acc[2][4][4];
#pragma unroll
        for (int m = 0; m < 2; ++m)
#pragma unroll
            for (int n = 0; n < 4; ++n)
#pragma unroll
                for (int f = 0; f < 4; ++f) acc[m][n][f] = 0.0f;

        int b = 0;
        for (int t = 0; t < cnt; ++t) {
            bar_sync(BAR_FULL + b, 512);
            const uint32_t sb = s0 + (uint32_t)b * BUF_BYTES;

#pragma unroll
            for (int ks = 0; ks < 4; ++ks) {
                const uint32_t kterm = (uint32_t)(ks * 32) + khalf;
                const uint32_t ka = kterm ^ axm;
                const uint32_t kb = kterm ^ bxm;

                uint32_t ah0[4], ah1[4], bha[4], bhb[4];
                ldsm4(ah0, sb + XH0 + aoff0 + ka);
                ldsm4(ah1, sb + XH0 + aoff1 + ka);
                ldsm4(bha, sb + WH0 + boff0 + kb);
                ldsm4(bhb, sb + WH0 + boff1 + kb);
                // hh
                mma16816(acc[0][0], ah0, bha[0], bha[2]);
                mma16816(acc[0][1], ah0, bha[1], bha[3]);
                mma16816(acc[0][2], ah0, bhb[0], bhb[2]);
                mma16816(acc[0][3], ah0, bhb[1], bhb[3]);
                mma16816(acc[1][0], ah1, bha[0], bha[2]);
                mma16816(acc[1][1], ah1, bha[1], bha[3]);
                mma16816(acc[1][2], ah1, bhb[0], bhb[2]);
                mma16816(acc[1][3], ah1, bhb[1], bhb[3]);
                {   // hl
                    uint32_t bla[4], blb[4];
                    ldsm4(bla, sb + WL0 + boff0 + kb);
                    ldsm4(blb, sb + WL0 + boff1 + kb);
                    mma16816(acc[0][0], ah0, bla[0], bla[2]);
                    mma16816(acc[0][1], ah0, bla[1], bla[3]);
                    mma16816(acc[0][2], ah0, blb[0], blb[2]);
                    mma16816(acc[0][3], ah0, blb[1], blb[3]);
                    mma16816(acc[1][0], ah1, bla[0], bla[2]);
                    mma16816(acc[1][1], ah1, bla[1], bla[3]);
                    mma16816(acc[1][2], ah1, blb[0], blb[2]);
                    mma16816(acc[1][3], ah1, blb[1], blb[3]);
                }
                {   // lh
                    uint32_t al0[4], al1[4];
                    ldsm4(al0, sb + XL0 + aoff0 + ka);
                    ldsm4(al1, sb + XL0 + aoff1 + ka);
                    mma16816(acc[0][0], al0, bha[0], bha[2]);
                    mma16816(acc[0][1], al0, bha[1], bha[3]);
                    mma16816(acc[0][2], al0, bhb[0], bhb[2]);
                    mma16816(acc[0][3], al0, bhb[1], bhb[3]);
                    mma16816(acc[1][0], al1, bha[0], bha[2]);
                    mma16816(acc[1][1], al1, bha[1], bha[3]);
                    mma16816(acc[1][2], al1, bhb[0], bhb[2]);
                    mma16816(acc[1][3], al1, bhb[1], bhb[3]);
                }
            }

            bar_arrive(BAR_EMPTY + b, 512);
            b = (b + 1 == NSTAGE) ? 0 : b + 1;
        }

        // ---- consumer-only epilogue: merge k-split pairs through smem ----
        bar_sync(BAR_CONS, 256);           // all consumers past their reads
        float* ebuf = (float*)dsmem;
        const int gr = lane >> 2;
        const int gc = (lane & 3) * 2;

        if (wk == 1) {
#pragma unroll
            for (int m = 0; m < 2; ++m)
#pragma unroll
                for (int n = 0; n < 4; ++n) {
                    const int rr = r0 + m * 16 + gr;
                    const int cc = c0 + n * 8 + gc;
                    *(float2*)&ebuf[rr * 64 + cc] =
                        make_float2(acc[m][n][0], acc[m][n][1]);
                    *(float2*)&ebuf[(rr + 8) * 64 + cc] =
                        make_float2(acc[m][n][2], acc[m][n][3]);
                }
        }
        bar_sync(BAR_CONS, 256);

        if (wk == 0) {
            float* dst = g_partials + (long)bid * 4096;
#pragma unroll
            for (int m = 0; m < 2; ++m)
#pragma unroll
                for (int n = 0; n < 4; ++n) {
                    const int rr = r0 + m * 16 + gr;
                    const int cc = c0 + n * 8 + gc;
                    float2 e0 = *(float2*)&ebuf[rr * 64 + cc];
                    float2 e1 = *(float2*)&ebuf[(rr + 8) * 64 + cc];
                    *(float2*)&dst[rr * 64 + cc] =
                        make_float2(acc[m][n][0] + e0.x, acc[m][n][1] + e0.y);
                    *(float2*)&dst[(rr + 8) * 64 + cc] =
                        make_float2(acc[m][n][2] + e1.x, acc[m][n][3] + e1.y);
                }
        }
    }
}

// ---------------- stage-1 reduce: 148 partials -> 32 (full chip) ----------------

__global__ __launch_bounds__(256) void reduce1_kernel() {
    const int bidx = blockIdx.x;          // 512 CTAs = 16 ogroups x 32 pgroups
    const int og = bidx & 15;
    const int pg = bidx >> 4;
    const int o  = og * 256 + threadIdx.x;   // 0..4095

    // 148 = 20*5 + 12*4
    const int base = (pg < 20) ? pg * 5 : 100 + (pg - 20) * 4;
    const int cnt  = (pg < 20) ? 5 : 4;

    float sum = 0.0f;
#pragma unroll 5
    for (int i = 0; i < cnt; ++i)
        sum += g_partials[(long)(base + i) * 4096 + o];
    g_s1[(long)pg * 4096 + o] = sum;
}

// ---------------- finalize: reduce 32 + bias + top-k + softmax ----------------

__global__ __launch_bounds__(256) void finalize_kernel(
    const float* __restrict__ bias, const int* __restrict__ kp,
    float* __restrict__ out) {
    const int b = blockIdx.x;
    const int t = threadIdx.x;
    const int e = t & 63;
    const int p = t >> 6;

    float sum = 0.0f;
#pragma unroll
    for (int j = 0; j < 8; ++j)
        sum += g_s1[(long)(p * 8 + j) * 4096 + b * 64 + e];

    __shared__ float acc[4][64];
    __shared__ float ys[64];
    __shared__ float evs[64];

    acc[p][e] = sum;
    __syncthreads();
    if (p == 0)
        ys[e] = acc[0][e] + acc[1][e] + acc[2][e] + acc[3][e] + bias[e];
    __syncthreads();

    const float yv = ys[e];
    const int kk = *kp;
    int rank = 0;
#pragma unroll 8
    for (int j = 0; j < 64; ++j) {
        const float yj = ys[j];
        rank += (yj > yv) || (yj == yv && j < e);
    }
    const float ev = (rank < kk) ? expf(yv) : 1.0f;
    if (p == 0) evs[e] = ev;
    __syncthreads();

    for (int off = 32; off > 0; off >>= 1) {
        if (t < off) evs[t] += evs[t + off];
        __syncthreads();
    }
    const float denom = evs[0];

    if (p == 0) out[b * 64 + e] = ev / denom;
}

extern "C" void kernel_launch(void* const* d_in, const int* in_sizes, int n_in,
                              void* d_out, int out_size) {
    const float* x    = (const float*)d_in[0];
    const float* W    = (const float*)d_in[1];
    const float* bias = (const float*)d_in[2];
    const int*   kp   = (const int*)d_in[3];
    float* out = (float*)d_out;

    cudaFuncSetAttribute(gemm_ws_kernel,
                         cudaFuncAttributeMaxDynamicSharedMemorySize,
                         NSTAGE * BUF_BYTES);
    gemm_ws_kernel<<<NBLK, 512, NSTAGE * BUF_BYTES>>>(x, W);
    reduce1_kernel<<<512, 256>>>();
    finalize_kernel<<<64, 256>>>(bias, kp, out);
}

// round 11
// speedup vs baseline: 1.0785x; 1.0785x over previous
#include <cuda_runtime.h>
#include <cuda_bf16.h>
#include <cstdint>

// TopKRoute: y = x.reshape(64, 786432) @ W^T + b ; scatter top-k ; softmax(64)
// Round 11: warp-specialized split-bf16 HMMA GEMM at occupancy 3.
//   444 CTAs x 256 threads (4 producer + 4 consumer warps), 2-stage 32KB ring
//   (64KB/CTA -> 192KB/SM at occ 3). Producer chunked to fit 84-reg cap.
//   Consumers: full-k 32x32 quadrants (no merge). Two-stage reduction tail.

#define K_TOTAL     786432
#define NBLK        444
#define TILE_K      64
#define TILES_TOTAL (K_TOTAL / TILE_K)        // 12288
#define BASE_T      (TILES_TOTAL / NBLK)      // 27
#define EXTRA_T     (TILES_TOTAL % NBLK)      // 300

#define NSTAGE 2
// regions within one 32KB stage buffer:
#define XH_OFF 0
#define XL_OFF 8192
#define WH_OFF 16384
#define WL_OFF 24576
#define BUF_BYTES 32768

// named barrier ids: FULL 1..2, EMPTY 3..4
#define BAR_FULL  1
#define BAR_EMPTY 3

__device__ float g_partials[NBLK * 64 * 64];   // 7.3 MB
__device__ float g_s1[32 * 64 * 64];           // stage-1 reduced partials

// ---------------- helpers ----------------

__device__ __forceinline__ uint32_t smem_u32(const void* p) {
    return (uint32_t)__cvta_generic_to_shared(p);
}

__device__ __forceinline__ void bar_sync(int id) {
    asm volatile("bar.sync %0, 256;" :: "r"(id) : "memory");
}
__device__ __forceinline__ void bar_arrive(int id) {
    asm volatile("bar.arrive %0, 256;" :: "r"(id) : "memory");
}

__device__ __forceinline__ void ldsm4(uint32_t* r, uint32_t addr) {
    asm volatile("ldmatrix.sync.aligned.m8n8.x4.shared.b16 {%0,%1,%2,%3}, [%4];"
                 : "=r"(r[0]), "=r"(r[1]), "=r"(r[2]), "=r"(r[3]) : "r"(addr));
}

__device__ __forceinline__ void mma16816(float* c, const uint32_t* a,
                                         uint32_t b0, uint32_t b1) {
    asm volatile(
        "mma.sync.aligned.m16n8k16.row.col.f32.bf16.bf16.f32 "
        "{%0,%1,%2,%3}, {%4,%5,%6,%7}, {%8,%9}, {%0,%1,%2,%3};"
        : "+f"(c[0]), "+f"(c[1]), "+f"(c[2]), "+f"(c[3])
        : "r"(a[0]), "r"(a[1]), "r"(a[2]), "r"(a[3]), "r"(b0), "r"(b1));
}

__device__ __forceinline__ void split4(float4 v, uint2& hi, uint2& lo) {
    __nv_bfloat162 h0 = __float22bfloat162_rn(make_float2(v.x, v.y));
    __nv_bfloat162 h1 = __float22bfloat162_rn(make_float2(v.z, v.w));
    float2 f0 = __bfloat1622float2(h0);
    float2 f1 = __bfloat1622float2(h1);
    __nv_bfloat162 l0 = __float22bfloat162_rn(make_float2(v.x - f0.x, v.y - f0.y));
    __nv_bfloat162 l1 = __float22bfloat162_rn(make_float2(v.z - f1.x, v.w - f1.y));
    hi.x = *(uint32_t*)&h0;  hi.y = *(uint32_t*)&h1;
    lo.x = *(uint32_t*)&l0;  lo.y = *(uint32_t*)&l1;
}

__device__ __forceinline__ uint32_t sw128(uint32_t off) {
    return off ^ ((off >> 3) & 0x70);
}

// ---------------- GEMM kernel ----------------

extern __shared__ char dsmem[];

__global__ __launch_bounds__(256, 3) void gemm_ws_kernel(
    const float* __restrict__ x, const float* __restrict__ W) {
    const int tid  = threadIdx.x;
    const int wid  = tid >> 5;
    const int lane = tid & 31;
    const int bid  = blockIdx.x;

    const int t0  = BASE_T * bid + (bid < EXTRA_T ? bid : EXTRA_T);
    const int cnt = BASE_T + (bid < EXTRA_T ? 1 : 0);
    const long kbase = (long)t0 * TILE_K;

    if (wid < 4) {
        // ================= PRODUCER: 128 threads =================
        // q = tid&15 (float4 col), rb = tid>>4 (0..7); rows rb + 8i, i 0..7.
        // Chunked (4 rows at a time) to cap live registers for occ 3.
        const int q  = tid & 15;
        const int rb = tid >> 4;
        const float* xp = x + (long)rb * K_TOTAL + kbase + q * 4;
        const float* wp = W + (long)rb * K_TOTAL + kbase + q * 4;
        const long rstep = 8L * K_TOTAL;

        uint32_t soff[8];
#pragma unroll
        for (int i = 0; i < 8; ++i)
            soff[i] = sw128((uint32_t)((rb + 8 * i) * 128 + q * 8));

        int b = 0;
        for (int t = 0; t < cnt; ++t) {
            if (t >= NSTAGE) bar_sync(BAR_EMPTY + b);
            char* buf = dsmem + b * BUF_BYTES;
            const long koff = (long)t * TILE_K;

#pragma unroll
            for (int c = 0; c < 2; ++c) {          // x in two 4-row chunks
                float4 v[4];
#pragma unroll
                for (int i = 0; i < 4; ++i)
                    v[i] = *(const float4*)(xp + (c * 4 + i) * rstep + koff);
#pragma unroll
                for (int i = 0; i < 4; ++i) {
                    uint2 hi, lo;
                    split4(v[i], hi, lo);
                    *(uint2*)(buf + XH_OFF + soff[c * 4 + i]) = hi;
                    *(uint2*)(buf + XL_OFF + soff[c * 4 + i]) = lo;
                }
            }
#pragma unroll
            for (int c = 0; c < 2; ++c) {          // w in two 4-row chunks
                float4 v[4];
#pragma unroll
                for (int i = 0; i < 4; ++i)
                    v[i] = *(const float4*)(wp + (c * 4 + i) * rstep + koff);
#pragma unroll
                for (int i = 0; i < 4; ++i) {
                    uint2 hi, lo;
                    split4(v[i], hi, lo);
                    *(uint2*)(buf + WH_OFF + soff[c * 4 + i]) = hi;
                    *(uint2*)(buf + WL_OFF + soff[c * 4 + i]) = lo;
                }
            }

            bar_arrive(BAR_FULL + b);
            b = (b + 1 == NSTAGE) ? 0 : b + 1;
        }
    } else {
        // ================= CONSUMER: 4 warps, 32x32 quadrants =================
        const int cwid = wid - 4;
        const int wr = cwid >> 1;
        const int wc = cwid & 1;
        const int r0 = wr * 32;
        const int c0 = wc * 32;

        const uint32_t s0 = smem_u32(dsmem);
        const int arow0 = r0 + (lane & 15);
        const int bcol0 = c0 + (lane & 15);
        const uint32_t axm   = (uint32_t)((arow0 & 7) * 16);
        const uint32_t bxm   = (uint32_t)((bcol0 & 7) * 16);
        const uint32_t khalf = (uint32_t)((lane >> 4) * 16);

        const uint32_t aoff0 = (uint32_t)(arow0 * 128);
        const uint32_t aoff1 = (uint32_t)((arow0 + 16) * 128);
        const uint32_t boff0 = (uint32_t)(bcol0 * 128);
        const uint32_t boff1 = (uint32_t)((bcol0 + 16) * 128);

        float acc[2][4][4];
#pragma unroll
        for (int m = 0; m < 2; ++m)
#pragma unroll
            for (int n = 0; n < 4; ++n)
#pragma unroll
                for (int f = 0; f < 4; ++f) acc[m][n][f] = 0.0f;

        int b = 0;
        for (int t = 0; t < cnt; ++t) {
            bar_sync(BAR_FULL + b);
            const uint32_t sb = s0 + (uint32_t)b * BUF_BYTES;

#pragma unroll
            for (int ks = 0; ks < 4; ++ks) {
                const uint32_t kterm = (uint32_t)(ks * 32) + khalf;
                const uint32_t ka = kterm ^ axm;
                const uint32_t kb = kterm ^ bxm;

                uint32_t ah0[4], ah1[4], bha[4], bhb[4];
                ldsm4(ah0, sb + XH_OFF + aoff0 + ka);
                ldsm4(ah1, sb + XH_OFF + aoff1 + ka);
                ldsm4(bha, sb + WH_OFF + boff0 + kb);
                ldsm4(bhb, sb + WH_OFF + boff1 + kb);
                // hh
                mma16816(acc[0][0], ah0, bha[0], bha[2]);
                mma16816(acc[0][1], ah0, bha[1], bha[3]);
                mma16816(acc[0][2], ah0, bhb[0], bhb[2]);
                mma16816(acc[0][3], ah0, bhb[1], bhb[3]);
                mma16816(acc[1][0], ah1, bha[0], bha[2]);
                mma16816(acc[1][1], ah1, bha[1], bha[3]);
                mma16816(acc[1][2], ah1, bhb[0], bhb[2]);
                mma16816(acc[1][3], ah1, bhb[1], bhb[3]);
                {   // hl: reuse ah, load wl frags
                    uint32_t bla[4], blb[4];
                    ldsm4(bla, sb + WL_OFF + boff0 + kb);
                    ldsm4(blb, sb + WL_OFF + boff1 + kb);
                    mma16816(acc[0][0], ah0, bla[0], bla[2]);
                    mma16816(acc[0][1], ah0, bla[1], bla[3]);
                    mma16816(acc[0][2], ah0, blb[0], blb[2]);
                    mma16816(acc[0][3], ah0, blb[1], blb[3]);
                    mma16816(acc[1][0], ah1, bla[0], bla[2]);
                    mma16816(acc[1][1], ah1, bla[1], bla[3]);
                    mma16816(acc[1][2], ah1, blb[0], blb[2]);
                    mma16816(acc[1][3], ah1, blb[1], blb[3]);
                }
                {   // lh: load xl frags, reuse bh
                    uint32_t al0[4], al1[4];
                    ldsm4(al0, sb + XL_OFF + aoff0 + ka);
                    ldsm4(al1, sb + XL_OFF + aoff1 + ka);
                    mma16816(acc[0][0], al0, bha[0], bha[2]);
                    mma16816(acc[0][1], al0, bha[1], bha[3]);
                    mma16816(acc[0][2], al0, bhb[0], bhb[2]);
                    mma16816(acc[0][3], al0, bhb[1], bhb[3]);
                    mma16816(acc[1][0], al1, bha[0], bha[2]);
                    mma16816(acc[1][1], al1, bha[1], bha[3]);
                    mma16816(acc[1][2], al1, bhb[0], bhb[2]);
                    mma16816(acc[1][3], al1, bhb[1], bhb[3]);
                }
            }

            bar_arrive(BAR_EMPTY + b);
            b = (b + 1 == NSTAGE) ? 0 : b + 1;
        }

        // epilogue: write quadrant directly (full-k accumulators, no merge)
        float* dst = g_partials + (long)bid * 4096;
        const int gr = lane >> 2;
        const int gc = (lane & 3) * 2;
#pragma unroll
        for (int m = 0; m < 2; ++m)
#pragma unroll
            for (int n = 0; n < 4; ++n) {
                const int rr = r0 + m * 16 + gr;
                const int cc = c0 + n * 8 + gc;
                *(float2*)&dst[rr * 64 + cc] =
                    make_float2(acc[m][n][0], acc[m][n][1]);
                *(float2*)&dst[(rr + 8) * 64 + cc] =
                    make_float2(acc[m][n][2], acc[m][n][3]);
            }
    }
}

// ---------------- stage-1 reduce: 444 partials -> 32 (full chip) ----------------

__global__ __launch_bounds__(256) void reduce1_kernel() {
    const int bidx = blockIdx.x;          // 512 CTAs = 16 ogroups x 32 pgroups
    const int og = bidx & 15;
    const int pg = bidx >> 4;
    const int o  = og * 256 + threadIdx.x;   // 0..4095

    // 444 = 28*14 + 4*13
    const int base = (pg < 28) ? pg * 14 : 392 + (pg - 28) * 13;
    const int cnt  = (pg < 28) ? 14 : 13;

    float sum = 0.0f;
#pragma unroll 14
    for (int i = 0; i < cnt; ++i)
        sum += g_partials[(long)(base + i) * 4096 + o];
    g_s1[(long)pg * 4096 + o] = sum;
}

// ---------------- finalize: reduce 32 + bias + top-k + softmax ----------------

__global__ __launch_bounds__(256) void finalize_kernel(
    const float* __restrict__ bias, const int* __restrict__ kp,
    float* __restrict__ out) {
    const int b = blockIdx.x;
    const int t = threadIdx.x;
    const int e = t & 63;
    const int p = t >> 6;

    float sum = 0.0f;
#pragma unroll
    for (int j = 0; j < 8; ++j)
        sum += g_s1[(long)(p * 8 + j) * 4096 + b * 64 + e];

    __shared__ float acc[4][64];
    __shared__ float ys[64];
    __shared__ float evs[64];

    acc[p][e] = sum;
    __syncthreads();
    if (p == 0)
        ys[e] = acc[0][e] + acc[1][e] + acc[2][e] + acc[3][e] + bias[e];
    __syncthreads();

    const float yv = ys[e];
    const int kk = *kp;
    int rank = 0;
#pragma unroll 8
    for (int j = 0; j < 64; ++j) {
        const float yj = ys[j];
        rank += (yj > yv) || (yj == yv && j < e);
    }
    const float ev = (rank < kk) ? expf(yv) : 1.0f;
    if (p == 0) evs[e] = ev;
    __syncthreads();

    for (int off = 32; off > 0; off >>= 1) {
        if (t < off) evs[t] += evs[t + off];
        __syncthreads();
    }
    const float denom = evs[0];

    if (p == 0) out[b * 64 + e] = ev / denom;
}

extern "C" void kernel_launch(void* const* d_in, const int* in_sizes, int n_in,
                              void* d_out, int out_size) {
    const float* x    = (const float*)d_in[0];
    const float* W    = (const float*)d_in[1];
    const float* bias = (const float*)d_in[2];
    const int*   kp   = (const int*)d_in[3];
    float* out = (float*)d_out;

    cudaFuncSetAttribute(gemm_ws_kernel,
                         cudaFuncAttributeMaxDynamicSharedMemorySize,
                         NSTAGE * BUF_BYTES);
    gemm_ws_kernel<<<NBLK, 256, NSTAGE * BUF_BYTES>>>(x, W);
    reduce1_kernel<<<512, 256>>>();
    finalize_kernel<<<64, 256>>>(bias, kp, out);
}